// round 12
// baseline (speedup 1.0000x reference)
#include <cuda_runtime.h>
#include <math.h>

#define B 8
#define C 256
#define H 128
#define W 128
#define OH 65
#define OW 65
#define HW (H*W)          // 16384
#define OHW (OH*OW)       // 4225
#define NPIX (B*OHW)      // 33800
#define SPLIT 8           // channel splits in norm kernel
#define CPS (C/SPLIT)     // 32 channels per split
#define CSPLIT 2          // channel halves in gather
#define CPW 16            // channels per warp (8 warps * 16 * 2 = 256)

// Scratch: device globals
__device__ float g_part[SPLIT*B*HW];     // 4 MB
__device__ float g_wts[9*NPIX];          // ~1.22 MB, layout [k][pixel]

// ---------------------------------------------------------------------------
// Kernel 1: partial channel sum-of-squares (proven config).
// ---------------------------------------------------------------------------
__global__ __launch_bounds__(128) void norm_part_kernel(const float* __restrict__ x) {
    int t   = threadIdx.x;
    int w4  = t & 31;
    int hl  = t >> 5;
    int bh4 = blockIdx.x;
    int b   = bh4 >> 5;
    int h   = ((bh4 & 31) << 2) + hl;
    int c0  = blockIdx.y * CPS;

    const float4* p = (const float4*)(x + ((size_t)(b * C + c0)) * HW + (size_t)h * W) + w4;

    float sx = 0.f, sy = 0.f, sz = 0.f, sw = 0.f;
    #pragma unroll 8
    for (int c = 0; c < CPS; c++) {
        float4 v = p[(size_t)c * (HW / 4)];
        sx = fmaf(v.x, v.x, sx);
        sy = fmaf(v.y, v.y, sy);
        sz = fmaf(v.z, v.z, sz);
        sw = fmaf(v.w, v.w, sw);
    }

    float4 o = make_float4(sx, sy, sz, sw);
    ((float4*)g_part)[(size_t)blockIdx.y * (B * HW / 4) + ((size_t)(b * H + h) * W) / 4 + w4] = o;
}

// ---------------------------------------------------------------------------
// Kernel 2 (fused reduce+sqrt+softmax): reads g_part directly (8 partials
// per norm position), softmax over 3x3 window, store transposed [k][pixel].
// ---------------------------------------------------------------------------
__global__ __launch_bounds__(256) void wts_kernel() {
    int idx = blockIdx.x * blockDim.x + threadIdx.x;
    if (idx >= NPIX) return;
    int ox = idx % OW;
    int t  = idx / OW;
    int oy = t % OH;
    int b  = t / OH;

    int iy0 = 2 * oy - 2;
    int ix0 = 2 * ox - 2;

    float v[9];
    #pragma unroll
    for (int i = 0; i < 3; i++) {
        int iy = iy0 + i;
        bool rok = (unsigned)iy < (unsigned)H;
        #pragma unroll
        for (int j = 0; j < 3; j++) {
            int ix = ix0 + j;
            bool ok = rok && ((unsigned)ix < (unsigned)W);
            float s = 0.f;
            if (ok) {
                int off = (b * H + iy) * W + ix;
                #pragma unroll
                for (int sp = 0; sp < SPLIT; sp++)
                    s += g_part[(size_t)sp * (B * HW) + off];
                s = sqrtf(s);
            }
            v[i * 3 + j] = s;
        }
    }

    float m = v[0];
    #pragma unroll
    for (int k = 1; k < 9; k++) m = fmaxf(m, v[k]);

    float e[9], sum = 0.f;
    #pragma unroll
    for (int k = 0; k < 9; k++) { e[k] = expf(v[k] - m); sum += e[k]; }
    float inv = 1.f / sum;

    #pragma unroll
    for (int k = 0; k < 9; k++) g_wts[k * NPIX + idx] = e[k] * inv;
}

// ---------------------------------------------------------------------------
// Kernel 3: register-stencil gather, 2-channel interleave.
// Block = (b, channel-half, oy), 256 thr, 8 warps. Per iteration a warp
// loads 6 independent LDG.128 (2 channels x 3 rows), then shfl+fma.
// Lane l -> ox=2l,2l+1; lane 31 also ox=64.
// ---------------------------------------------------------------------------
__global__ __launch_bounds__(256) void gather_kernel(const float* __restrict__ x,
                                                     float* __restrict__ out) {
    int bid = blockIdx.x;                 // ((b*CSPLIT+cs)*OH + oy)
    int oy  = bid % OH;
    int t2  = bid / OH;
    int cs  = t2 & (CSPLIT - 1);
    int b   = t2 / CSPLIT;

    int warp = threadIdx.x >> 5;
    int lane = threadIdx.x & 31;

    // ---- Weights ----
    int pixb = (b * OH + oy) * OW;
    float wA[9], wB[9], wC[6];            // wC: ox=64 taps j=0,1 only (j=2 pad)
    #pragma unroll
    for (int k = 0; k < 9; k++) {
        wA[k] = g_wts[k * NPIX + pixb + 2 * lane];
        wB[k] = g_wts[k * NPIX + pixb + 2 * lane + 1];
    }
    #pragma unroll
    for (int i = 0; i < 3; i++) {
        wC[i*2+0] = g_wts[(i*3+0) * NPIX + pixb + 64];
        wC[i*2+1] = g_wts[(i*3+1) * NPIX + pixb + 64];
    }
    if (lane == 0) {
        #pragma unroll
        for (int i = 0; i < 3; i++) { wA[i*3+0] = 0.f; wA[i*3+1] = 0.f; }
    }

    // Row clamps + pad zeroing.
    int iy0 = 2 * oy - 2;
    int iyv[3];
    #pragma unroll
    for (int i = 0; i < 3; i++) {
        int iy = iy0 + i;
        if (iy < 0 || iy >= H) {
            iy = iy < 0 ? 0 : H - 1;
            wA[i*3] = wA[i*3+1] = wA[i*3+2] = 0.f;
            wB[i*3] = wB[i*3+1] = wB[i*3+2] = 0.f;
            wC[i*2] = wC[i*2+1] = 0.f;
        }
        iyv[i] = iy;
    }
    int r0 = iyv[0] * W, r1 = iyv[1] * W, r2 = iyv[2] * W;

    const float* xbase = x + (size_t)(b * C + cs * (C / CSPLIT)) * HW;
    float* obase = out + (size_t)(b * C + cs * (C / CSPLIT)) * OHW + (size_t)oy * OW;

    #pragma unroll 2
    for (int ci = 0; ci < CPW / 2; ci++) {
        int c0 = warp * CPW + 2 * ci;     // warp-local channel pair
        const float* rb0 = xbase + (size_t)c0 * HW;
        const float* rb1 = rb0 + HW;

        // ---- 6 independent dense loads ----
        float4 u0 = ((const float4*)(rb0 + r0))[lane];
        float4 u1 = ((const float4*)(rb0 + r1))[lane];
        float4 u2 = ((const float4*)(rb0 + r2))[lane];
        float4 v0 = ((const float4*)(rb1 + r0))[lane];
        float4 v1 = ((const float4*)(rb1 + r1))[lane];
        float4 v2 = ((const float4*)(rb1 + r2))[lane];

        float a0 = 0.f, a1 = 0.f, a2 = 0.f;   // ch0: ox0, ox1, ox64
        float b0 = 0.f, b1 = 0.f, b2 = 0.f;   // ch1

        #pragma unroll
        for (int i = 0; i < 3; i++) {
            float4 u = i == 0 ? u0 : (i == 1 ? u1 : u2);
            float4 v = i == 0 ? v0 : (i == 1 ? v1 : v2);
            float upz = __shfl_up_sync(0xFFFFFFFFu, u.z, 1);
            float upw = __shfl_up_sync(0xFFFFFFFFu, u.w, 1);
            float vpz = __shfl_up_sync(0xFFFFFFFFu, v.z, 1);
            float vpw = __shfl_up_sync(0xFFFFFFFFu, v.w, 1);

            a0 = fmaf(wA[i*3+0], upz, a0);
            a0 = fmaf(wA[i*3+1], upw, a0);
            a0 = fmaf(wA[i*3+2], u.x, a0);
            a1 = fmaf(wB[i*3+0], u.x, a1);
            a1 = fmaf(wB[i*3+1], u.y, a1);
            a1 = fmaf(wB[i*3+2], u.z, a1);
            a2 = fmaf(wC[i*2+0], u.z, a2);
            a2 = fmaf(wC[i*2+1], u.w, a2);

            b0 = fmaf(wA[i*3+0], vpz, b0);
            b0 = fmaf(wA[i*3+1], vpw, b0);
            b0 = fmaf(wA[i*3+2], v.x, b0);
            b1 = fmaf(wB[i*3+0], v.x, b1);
            b1 = fmaf(wB[i*3+1], v.y, b1);
            b1 = fmaf(wB[i*3+2], v.z, b1);
            b2 = fmaf(wC[i*2+0], v.z, b2);
            b2 = fmaf(wC[i*2+1], v.w, b2);
        }

        float* o0 = obase + (size_t)c0 * OHW;
        float* o1 = o0 + OHW;
        o0[2 * lane]     = a0;
        o0[2 * lane + 1] = a1;
        o1[2 * lane]     = b0;
        o1[2 * lane + 1] = b1;
        if (lane == 31) { o0[64] = a2; o1[64] = b2; }
    }
}

// ---------------------------------------------------------------------------
extern "C" void kernel_launch(void* const* d_in, const int* in_sizes, int n_in,
                              void* d_out, int out_size) {
    const float* x = (const float*)d_in[0];
    float* out = (float*)d_out;

    dim3 g1(B * H / 4, SPLIT);                   // 2048 blocks
    norm_part_kernel<<<g1, 128>>>(x);

    wts_kernel<<<(NPIX + 255) / 256, 256>>>();   // fused reduce+softmax

    int n3 = B * CSPLIT * OH;                    // 1040 blocks
    gather_kernel<<<n3, 256>>>(x, out);
}

// round 13
// speedup vs baseline: 1.0993x; 1.0993x over previous
#include <cuda_runtime.h>
#include <math.h>

#define B 8
#define C 256
#define H 128
#define W 128
#define OH 65
#define OW 65
#define HW (H*W)          // 16384
#define OHW (OH*OW)       // 4225
#define NPIX (B*OHW)      // 33800
#define SPLIT 8
#define CPS (C/SPLIT)     // 32
#define CSPLIT 2
#define CPW 16            // channels per warp (8 warps * 16 * 2 = 256)

__device__ float g_part[SPLIT*B*HW];     // 4 MB
__device__ float g_norm[B*HW];           // 512 KB
__device__ float g_wts[9*NPIX];          // ~1.22 MB, [k][pixel]

// ---------------------------------------------------------------------------
// Kernel 1: partial channel sum-of-squares, float4, 8-way split, deep unroll.
// ---------------------------------------------------------------------------
__global__ __launch_bounds__(128) void norm_part_kernel(const float* __restrict__ x) {
    int t   = threadIdx.x;
    int w4  = t & 31;
    int hl  = t >> 5;
    int bh4 = blockIdx.x;
    int b   = bh4 >> 5;
    int h   = ((bh4 & 31) << 2) + hl;
    int c0  = blockIdx.y * CPS;

    const float4* p = (const float4*)(x + ((size_t)(b * C + c0)) * HW + (size_t)h * W) + w4;

    float sx = 0.f, sy = 0.f, sz = 0.f, sw = 0.f;
    #pragma unroll 16
    for (int c = 0; c < CPS; c++) {
        float4 v = __ldcs(p + (size_t)c * (HW / 4));
        sx = fmaf(v.x, v.x, sx);
        sy = fmaf(v.y, v.y, sy);
        sz = fmaf(v.z, v.z, sz);
        sw = fmaf(v.w, v.w, sw);
    }

    float4 o = make_float4(sx, sy, sz, sw);
    __stcs(((float4*)g_part) + (size_t)blockIdx.y * (B * HW / 4)
                             + ((size_t)(b * H + h) * W) / 4 + w4, o);
}

// ---------------------------------------------------------------------------
// Kernel 2: reduce partials + sqrt -> g_norm.
// ---------------------------------------------------------------------------
__global__ __launch_bounds__(256) void norm_reduce_kernel() {
    int i = blockIdx.x * blockDim.x + threadIdx.x;
    if (i >= B * HW / 4) return;
    const float4* p = (const float4*)g_part;
    float4 a = __ldcs(p + i);
    #pragma unroll
    for (int s = 1; s < SPLIT; s++) {
        float4 v = __ldcs(p + (size_t)s * (B * HW / 4) + i);
        a.x += v.x; a.y += v.y; a.z += v.z; a.w += v.w;
    }
    a.x = sqrtf(a.x); a.y = sqrtf(a.y); a.z = sqrtf(a.z); a.w = sqrtf(a.w);
    ((float4*)g_norm)[i] = a;
}

// ---------------------------------------------------------------------------
// Kernel 3: softmax weights, layout [k][pixel].
// ---------------------------------------------------------------------------
__global__ __launch_bounds__(256) void wts_kernel() {
    int idx = blockIdx.x * blockDim.x + threadIdx.x;
    if (idx >= NPIX) return;
    int ox = idx % OW;
    int t  = idx / OW;
    int oy = t % OH;
    int b  = t / OH;

    int iy0 = 2 * oy - 2;
    int ix0 = 2 * ox - 2;

    float v[9];
    #pragma unroll
    for (int i = 0; i < 3; i++) {
        int iy = iy0 + i;
        bool rok = (unsigned)iy < (unsigned)H;
        #pragma unroll
        for (int j = 0; j < 3; j++) {
            int ix = ix0 + j;
            bool ok = rok && ((unsigned)ix < (unsigned)W);
            v[i * 3 + j] = ok ? g_norm[(b * H + iy) * W + ix] : 0.f;
        }
    }

    float m = v[0];
    #pragma unroll
    for (int k = 1; k < 9; k++) m = fmaxf(m, v[k]);

    float e[9], sum = 0.f;
    #pragma unroll
    for (int k = 0; k < 9; k++) { e[k] = expf(v[k] - m); sum += e[k]; }
    float inv = 1.f / sum;

    #pragma unroll
    for (int k = 0; k < 9; k++) __stcs(&g_wts[k * NPIX + idx], e[k] * inv);
}

// ---------------------------------------------------------------------------
// Kernel 4: register-stencil gather, 2-channel interleave, streaming hints.
// ---------------------------------------------------------------------------
__global__ __launch_bounds__(256) void gather_kernel(const float* __restrict__ x,
                                                     float* __restrict__ out) {
    int bid = blockIdx.x;                 // ((b*CSPLIT+cs)*OH + oy)
    int oy  = bid % OH;
    int t2  = bid / OH;
    int cs  = t2 & (CSPLIT - 1);
    int b   = t2 / CSPLIT;

    int warp = threadIdx.x >> 5;
    int lane = threadIdx.x & 31;

    int pixb = (b * OH + oy) * OW;
    float wA[9], wB[9], wC[6];
    #pragma unroll
    for (int k = 0; k < 9; k++) {
        wA[k] = g_wts[k * NPIX + pixb + 2 * lane];
        wB[k] = g_wts[k * NPIX + pixb + 2 * lane + 1];
    }
    #pragma unroll
    for (int i = 0; i < 3; i++) {
        wC[i*2+0] = g_wts[(i*3+0) * NPIX + pixb + 64];
        wC[i*2+1] = g_wts[(i*3+1) * NPIX + pixb + 64];
    }
    if (lane == 0) {
        #pragma unroll
        for (int i = 0; i < 3; i++) { wA[i*3+0] = 0.f; wA[i*3+1] = 0.f; }
    }

    int iy0 = 2 * oy - 2;
    int iyv[3];
    #pragma unroll
    for (int i = 0; i < 3; i++) {
        int iy = iy0 + i;
        if (iy < 0 || iy >= H) {
            iy = iy < 0 ? 0 : H - 1;
            wA[i*3] = wA[i*3+1] = wA[i*3+2] = 0.f;
            wB[i*3] = wB[i*3+1] = wB[i*3+2] = 0.f;
            wC[i*2] = wC[i*2+1] = 0.f;
        }
        iyv[i] = iy;
    }
    int r0 = iyv[0] * W, r1 = iyv[1] * W, r2 = iyv[2] * W;

    const float* xbase = x + (size_t)(b * C + cs * (C / CSPLIT)) * HW;
    float* obase = out + (size_t)(b * C + cs * (C / CSPLIT)) * OHW + (size_t)oy * OW;

    #pragma unroll 2
    for (int ci = 0; ci < CPW / 2; ci++) {
        int c0 = warp * CPW + 2 * ci;
        const float* rb0 = xbase + (size_t)c0 * HW;
        const float* rb1 = rb0 + HW;

        float4 u0 = __ldcs(((const float4*)(rb0 + r0)) + lane);
        float4 u1 = __ldcs(((const float4*)(rb0 + r1)) + lane);
        float4 u2 = __ldcs(((const float4*)(rb0 + r2)) + lane);
        float4 v0 = __ldcs(((const float4*)(rb1 + r0)) + lane);
        float4 v1 = __ldcs(((const float4*)(rb1 + r1)) + lane);
        float4 v2 = __ldcs(((const float4*)(rb1 + r2)) + lane);

        float a0 = 0.f, a1 = 0.f, a2 = 0.f;
        float b0 = 0.f, b1 = 0.f, b2 = 0.f;

        #pragma unroll
        for (int i = 0; i < 3; i++) {
            float4 u = i == 0 ? u0 : (i == 1 ? u1 : u2);
            float4 v = i == 0 ? v0 : (i == 1 ? v1 : v2);
            float upz = __shfl_up_sync(0xFFFFFFFFu, u.z, 1);
            float upw = __shfl_up_sync(0xFFFFFFFFu, u.w, 1);
            float vpz = __shfl_up_sync(0xFFFFFFFFu, v.z, 1);
            float vpw = __shfl_up_sync(0xFFFFFFFFu, v.w, 1);

            a0 = fmaf(wA[i*3+0], upz, a0);
            a0 = fmaf(wA[i*3+1], upw, a0);
            a0 = fmaf(wA[i*3+2], u.x, a0);
            a1 = fmaf(wB[i*3+0], u.x, a1);
            a1 = fmaf(wB[i*3+1], u.y, a1);
            a1 = fmaf(wB[i*3+2], u.z, a1);
            a2 = fmaf(wC[i*2+0], u.z, a2);
            a2 = fmaf(wC[i*2+1], u.w, a2);

            b0 = fmaf(wA[i*3+0], vpz, b0);
            b0 = fmaf(wA[i*3+1], vpw, b0);
            b0 = fmaf(wA[i*3+2], v.x, b0);
            b1 = fmaf(wB[i*3+0], v.x, b1);
            b1 = fmaf(wB[i*3+1], v.y, b1);
            b1 = fmaf(wB[i*3+2], v.z, b1);
            b2 = fmaf(wC[i*2+0], v.z, b2);
            b2 = fmaf(wC[i*2+1], v.w, b2);
        }

        float* o0 = obase + (size_t)c0 * OHW;
        float* o1 = o0 + OHW;
        __stcs(&o0[2 * lane],     a0);
        __stcs(&o0[2 * lane + 1], a1);
        __stcs(&o1[2 * lane],     b0);
        __stcs(&o1[2 * lane + 1], b1);
        if (lane == 31) { __stcs(&o0[64], a2); __stcs(&o1[64], b2); }
    }
}

// ---------------------------------------------------------------------------
extern "C" void kernel_launch(void* const* d_in, const int* in_sizes, int n_in,
                              void* d_out, int out_size) {
    const float* x = (const float*)d_in[0];
    float* out = (float*)d_out;

    dim3 g1(B * H / 4, SPLIT);                   // 2048 blocks
    norm_part_kernel<<<g1, 128>>>(x);

    int n2 = B * HW / 4;
    norm_reduce_kernel<<<(n2 + 255) / 256, 256>>>();

    wts_kernel<<<(NPIX + 255) / 256, 256>>>();

    int n4 = B * CSPLIT * OH;                    // 1040 blocks
    gather_kernel<<<n4, 256>>>(x, out);
}